// round 2
// baseline (speedup 1.0000x reference)
#include <cuda_runtime.h>

#define N_BATCH 4
#define C_TOTAL 2048
#define T_FR    8
#define HH      16
#define WW      16
#define R_ROIS  32
#define OUT_SZ  16
#define SCALE   (1.0f/16.0f)

#define C_CHUNKS 64
#define C_PER    (C_TOTAL / C_CHUNKS)   // 32 channels per block

#define OUT_ELEMS   (R_ROIS * C_TOTAL * OUT_SZ * OUT_SZ)   // 16777216
#define FEATP_ELEMS (N_BATCH * C_TOTAL * HH * WW)          // 2097152

// ---------------------------------------------------------------------------
// Kernel 1: temporal mean over T=8.  feat [N,C,T,16,16] -> feat_p [N,C,16,16]
// ---------------------------------------------------------------------------
__global__ void tmean_kernel(const float* __restrict__ feat,
                             float* __restrict__ featp) {
    int idx = blockIdx.x * blockDim.x + threadIdx.x;   // float4 index
    const int TOTAL4 = FEATP_ELEMS / 4;                // 524288
    if (idx >= TOTAL4) return;
    const float4* f4 = (const float4*)feat;
    int pix = idx & 63;          // float4 within one 16x16 plane
    int nc  = idx >> 6;
    long base = (long)nc * (T_FR * 64) + pix;
    float4 a = f4[base];
    #pragma unroll
    for (int t = 1; t < T_FR; t++) {
        float4 v = f4[base + (long)t * 64];
        a.x += v.x; a.y += v.y; a.z += v.z; a.w += v.w;
    }
    a.x *= 0.125f; a.y *= 0.125f; a.z *= 0.125f; a.w *= 0.125f;
    ((float4*)featp)[idx] = a;
}

// ---------------------------------------------------------------------------
// Kernel 2: aligned RoIAlign (avg, ratio=2) on feat_p.
// Block = (32-channel chunk, roi); 256 threads = one output pixel each.
// Stage all 32 planes in smem with ONE sync, then barrier-free compute.
// Per-thread sampling indices are deduplicated (linear gather => weights sum),
// cutting the 4x4 gather to typically 2x2.
// ---------------------------------------------------------------------------
__global__ __launch_bounds__(256) void roialign_kernel(
        const float* __restrict__ featp,
        const float* __restrict__ rois,
        float* __restrict__ out) {
    const int r     = blockIdx.y;
    const int cbase = blockIdx.x * C_PER;
    const int tid   = threadIdx.x;
    const int px    = tid & 15;
    const int py    = tid >> 4;

    __shared__ float tile[C_PER * HH * WW];   // 32 KB

    // --- geometry ---
    const float r0  = rois[r * 5 + 0];
    const float bx1 = rois[r * 5 + 1] * SCALE - 0.5f;
    const float by1 = rois[r * 5 + 2] * SCALE - 0.5f;
    const float bx2 = rois[r * 5 + 3] * SCALE - 0.5f;
    const float by2 = rois[r * 5 + 4] * SCALE - 0.5f;
    const int   nb  = (int)r0;
    const float bin_h = (by2 - by1) * (1.0f / OUT_SZ);
    const float bin_w = (bx2 - bx1) * (1.0f / OUT_SZ);

    // raw 4-term tables per axis (mask * 1/2 folded into weights)
    int   yi4[4]; float wy4[4];
    int   xi4[4]; float wx4[4];
    #pragma unroll
    for (int s = 0; s < 2; s++) {
        {   // y axis
            float g  = ((float)(2 * py + s) + 0.5f) * 0.5f;
            float ys = by1 + g * bin_h;
            float vm = (ys >= -1.0f && ys <= (float)HH) ? 0.5f : 0.0f;
            float y  = fminf(fmaxf(ys, 0.0f), (float)(HH - 1));
            float y0f = floorf(y);
            int   y0  = (int)y0f;
            int   y1  = min(y0 + 1, HH - 1);
            float ly  = y - y0f;
            yi4[2*s]   = y0; wy4[2*s]   = (1.0f - ly) * vm;
            yi4[2*s+1] = y1; wy4[2*s+1] = ly * vm;
        }
        {   // x axis
            float g  = ((float)(2 * px + s) + 0.5f) * 0.5f;
            float xs = bx1 + g * bin_w;
            float vm = (xs >= -1.0f && xs <= (float)WW) ? 0.5f : 0.0f;
            float x  = fminf(fmaxf(xs, 0.0f), (float)(WW - 1));
            float x0f = floorf(x);
            int   x0  = (int)x0f;
            int   x1  = min(x0 + 1, WW - 1);
            float lx  = x - x0f;
            xi4[2*s]   = x0; wx4[2*s]   = (1.0f - lx) * vm;
            xi4[2*s+1] = x1; wx4[2*s+1] = lx * vm;
        }
    }

    // --- dedup indices (gather is linear: equal indices => sum weights) ---
    int   YO[4]; float WY[4]; int ny = 0;
    int   XI[4]; float WX[4]; int nx = 0;
    #pragma unroll
    for (int k = 0; k < 4; k++) {
        if (wy4[k] != 0.0f) {
            bool merged = false;
            for (int j = 0; j < ny; j++)
                if (YO[j] == yi4[k] * WW) { WY[j] += wy4[k]; merged = true; break; }
            if (!merged) { YO[ny] = yi4[k] * WW; WY[ny] = wy4[k]; ny++; }
        }
        if (wx4[k] != 0.0f) {
            bool merged = false;
            for (int j = 0; j < nx; j++)
                if (XI[j] == xi4[k]) { WX[j] += wx4[k]; merged = true; break; }
            if (!merged) { XI[nx] = xi4[k]; WX[nx] = wx4[k]; nx++; }
        }
    }

    // --- cooperative stage of 32 planes (8 float4 per thread), one sync ---
    const float4* fp4 = (const float4*)featp + ((long)nb * C_TOTAL + cbase) * 64;
    float4* t4 = (float4*)tile;
    #pragma unroll
    for (int j = 0; j < (C_PER * HH * WW / 4) / 256; j++)   // 8
        t4[tid + j * 256] = fp4[tid + j * 256];
    __syncthreads();

    // --- barrier-free compute: 32 channels per thread ---
    float* op = out + ((long)r * C_TOTAL + cbase) * (HH * WW) + tid;
    #pragma unroll 4
    for (int i = 0; i < C_PER; i++) {
        const float* sh = tile + i * (HH * WW);
        float acc = 0.0f;
        for (int a = 0; a < ny; a++) {
            const float* row = sh + YO[a];
            float d = 0.0f;
            for (int k = 0; k < nx; k++)
                d = fmaf(WX[k], row[XI[k]], d);
            acc = fmaf(WY[a], d, acc);
        }
        op[(long)i * (HH * WW)] = acc;
    }
}

// ---------------------------------------------------------------------------
extern "C" void kernel_launch(void* const* d_in, const int* in_sizes, int n_in,
                              void* d_out, int out_size) {
    const float* feat = (const float*)d_in[0];
    const float* rois = (const float*)d_in[1];
    float* out   = (float*)d_out;
    float* featp = out + OUT_ELEMS;   // feat_p is the 2nd tuple element

    {   // temporal mean
        const int TOTAL4 = FEATP_ELEMS / 4;
        tmean_kernel<<<(TOTAL4 + 255) / 256, 256>>>(feat, featp);
    }
    {   // RoIAlign
        dim3 grid(C_CHUNKS, R_ROIS);   // 64 x 32 = 2048 blocks
        roialign_kernel<<<grid, 256>>>(featp, rois, out);
    }
}

// round 3
// speedup vs baseline: 1.8262x; 1.8262x over previous
#include <cuda_runtime.h>

#define N_BATCH 4
#define C_TOTAL 2048
#define T_FR    8
#define HH      16
#define WW      16
#define R_ROIS  32
#define OUT_SZ  16
#define SCALE   (1.0f/16.0f)

#define C_PER    16
#define C_CHUNKS (C_TOTAL / C_PER)      // 128

#define TSTR     17                      // padded tmp row stride
#define OUT_ELEMS   (R_ROIS * C_TOTAL * OUT_SZ * OUT_SZ)   // 16777216
#define FEATP_ELEMS (N_BATCH * C_TOTAL * HH * WW)          // 2097152

// ---------------------------------------------------------------------------
// Kernel 1: temporal mean over T=8.  feat [N,C,T,16,16] -> feat_p [N,C,16,16]
// ---------------------------------------------------------------------------
__global__ void tmean_kernel(const float* __restrict__ feat,
                             float* __restrict__ featp) {
    int idx = blockIdx.x * blockDim.x + threadIdx.x;   // float4 index
    const int TOTAL4 = FEATP_ELEMS / 4;                // 524288
    if (idx >= TOTAL4) return;
    const float4* f4 = (const float4*)feat;
    int pix = idx & 63;
    int nc  = idx >> 6;
    long base = (long)nc * (T_FR * 64) + pix;
    float4 a = f4[base];
    #pragma unroll
    for (int t = 1; t < T_FR; t++) {
        float4 v = f4[base + (long)t * 64];
        a.x += v.x; a.y += v.y; a.z += v.z; a.w += v.w;
    }
    a.x *= 0.125f; a.y *= 0.125f; a.z *= 0.125f; a.w *= 0.125f;
    ((float4*)featp)[idx] = a;
}

// ---------------------------------------------------------------------------
// Kernel 2: aligned RoIAlign (avg, ratio=2), separable two-pass in shared.
// Block = (16-channel chunk, roi); 256 threads.
//   stage: 16 planes -> smem (float4, 1 sync)
//   x-pass: thread (y, j) computes tmp[c][y][j] = sum_k WX[j][k]*plane[y][XI[k]]
//   (1 sync)
//   y-pass: thread (i, j) computes out = sum_a WY[i][a]*tmp[c][YO[a]][j]
// All tap loops are fixed length 4, fully unrolled; weights/indices in regs.
// ---------------------------------------------------------------------------
__global__ __launch_bounds__(256) void roialign_kernel(
        const float* __restrict__ featp,
        const float* __restrict__ rois,
        float* __restrict__ out) {
    const int r     = blockIdx.y;
    const int cbase = blockIdx.x * C_PER;
    const int tid   = threadIdx.x;
    const int lx    = tid & 15;     // x-pass: out col j   | y-pass: out col j
    const int ly    = tid >> 4;     // x-pass: feat row y  | y-pass: out row i

    __shared__ float in_tile[C_PER * HH * WW];      // 16 KB
    __shared__ float tmp[C_PER * HH * TSTR];        // 17 KB

    // --- geometry ---
    const float r0  = rois[r * 5 + 0];
    const float bx1 = rois[r * 5 + 1] * SCALE - 0.5f;
    const float by1 = rois[r * 5 + 2] * SCALE - 0.5f;
    const float bx2 = rois[r * 5 + 3] * SCALE - 0.5f;
    const float by2 = rois[r * 5 + 4] * SCALE - 0.5f;
    const int   nb  = (int)r0;
    const float bin_h = (by2 - by1) * (1.0f / OUT_SZ);
    const float bin_w = (bx2 - bx1) * (1.0f / OUT_SZ);

    // x taps for output column lx; y taps for output row ly (mask*0.5 folded)
    int   XI[4]; float WX[4];
    int   YO[4]; float WY[4];       // YO holds y*TSTR for the y-pass
    #pragma unroll
    for (int s = 0; s < 2; s++) {
        {   // x axis (uses lx)
            float g  = ((float)(2 * lx + s) + 0.5f) * 0.5f;
            float xs = bx1 + g * bin_w;
            float vm = (xs >= -1.0f && xs <= (float)WW) ? 0.5f : 0.0f;
            float x  = fminf(fmaxf(xs, 0.0f), (float)(WW - 1));
            float x0f = floorf(x);
            int   x0  = (int)x0f;
            int   x1  = min(x0 + 1, WW - 1);
            float lxf = x - x0f;
            XI[2*s]   = x0; WX[2*s]   = (1.0f - lxf) * vm;
            XI[2*s+1] = x1; WX[2*s+1] = lxf * vm;
        }
        {   // y axis (uses ly)
            float g  = ((float)(2 * ly + s) + 0.5f) * 0.5f;
            float ys = by1 + g * bin_h;
            float vm = (ys >= -1.0f && ys <= (float)HH) ? 0.5f : 0.0f;
            float y  = fminf(fmaxf(ys, 0.0f), (float)(HH - 1));
            float y0f = floorf(y);
            int   y0  = (int)y0f;
            int   y1  = min(y0 + 1, HH - 1);
            float lyf = y - y0f;
            YO[2*s]   = y0 * TSTR; WY[2*s]   = (1.0f - lyf) * vm;
            YO[2*s+1] = y1 * TSTR; WY[2*s+1] = lyf * vm;
        }
    }

    // --- stage 16 planes (4 float4 per thread), one sync ---
    {
        const float4* fp4 = (const float4*)featp + ((long)nb * C_TOTAL + cbase) * 64;
        float4* t4 = (float4*)in_tile;
        #pragma unroll
        for (int j = 0; j < (C_PER * HH * WW / 4) / 256; j++)   // 4
            t4[tid + j * 256] = fp4[tid + j * 256];
    }
    __syncthreads();

    // --- x-pass: tmp[c][ly][lx] ---
    {
        const float* src = in_tile + ly * WW;          // row ly of channel 0
        float*       dst = tmp + ly * TSTR + lx;
        #pragma unroll
        for (int c = 0; c < C_PER; c++) {
            const float* row = src + c * (HH * WW);
            float v;
            v = WX[0] * row[XI[0]];
            v = fmaf(WX[1], row[XI[1]], v);
            v = fmaf(WX[2], row[XI[2]], v);
            v = fmaf(WX[3], row[XI[3]], v);
            dst[c * (HH * TSTR)] = v;
        }
    }
    __syncthreads();

    // --- y-pass: out[r][c][ly][lx] ---
    {
        const float* tc = tmp + lx;
        float* op = out + ((long)r * C_TOTAL + cbase) * (HH * WW) + tid;
        #pragma unroll
        for (int c = 0; c < C_PER; c++) {
            const float* col = tc + c * (HH * TSTR);
            float acc;
            acc = WY[0] * col[YO[0]];
            acc = fmaf(WY[1], col[YO[1]], acc);
            acc = fmaf(WY[2], col[YO[2]], acc);
            acc = fmaf(WY[3], col[YO[3]], acc);
            op[c * (HH * WW)] = acc;
        }
    }
}

// ---------------------------------------------------------------------------
extern "C" void kernel_launch(void* const* d_in, const int* in_sizes, int n_in,
                              void* d_out, int out_size) {
    const float* feat = (const float*)d_in[0];
    const float* rois = (const float*)d_in[1];
    float* out   = (float*)d_out;
    float* featp = out + OUT_ELEMS;   // feat_p is the 2nd tuple element

    {   // temporal mean
        const int TOTAL4 = FEATP_ELEMS / 4;
        tmean_kernel<<<(TOTAL4 + 255) / 256, 256>>>(feat, featp);
    }
    {   // RoIAlign
        dim3 grid(C_CHUNKS, R_ROIS);   // 128 x 32 = 4096 blocks
        roialign_kernel<<<grid, 256>>>(featp, rois, out);
    }
}

// round 4
// speedup vs baseline: 2.0629x; 1.1296x over previous
#include <cuda_runtime.h>

#define N_BATCH 4
#define C_TOTAL 2048
#define T_FR    8
#define HH      16
#define WW      16
#define R_ROIS  32
#define OUT_SZ  16
#define SCALE   (1.0f/16.0f)

#define C_PER    16
#define C_CHUNKS (C_TOTAL / C_PER)      // 128

#define TSTR     17                      // padded tmp row stride
#define OUT_ELEMS   (R_ROIS * C_TOTAL * OUT_SZ * OUT_SZ)   // 16777216
#define FEATP_ELEMS (N_BATCH * C_TOTAL * HH * WW)          // 2097152

// ---------------------------------------------------------------------------
// Kernel 1: temporal mean over T=8.  feat [N,C,T,16,16] -> feat_p [N,C,16,16]
// ---------------------------------------------------------------------------
__global__ void tmean_kernel(const float* __restrict__ feat,
                             float* __restrict__ featp) {
    int idx = blockIdx.x * blockDim.x + threadIdx.x;   // float4 index
    const int TOTAL4 = FEATP_ELEMS / 4;                // 524288
    if (idx >= TOTAL4) return;
    const float4* f4 = (const float4*)feat;
    int pix = idx & 63;
    int nc  = idx >> 6;
    long base = (long)nc * (T_FR * 64) + pix;
    float4 a = f4[base];
    #pragma unroll
    for (int t = 1; t < T_FR; t++) {
        float4 v = f4[base + (long)t * 64];
        a.x += v.x; a.y += v.y; a.z += v.z; a.w += v.w;
    }
    a.x *= 0.125f; a.y *= 0.125f; a.z *= 0.125f; a.w *= 0.125f;
    ((float4*)featp)[idx] = a;
}

// Build 3-tap (index, weight) table for one axis / one output coordinate u.
// With ratio=2, the two samples' floors differ by <=1, so all 4 bilinear taps
// fit in 3 consecutive cells {f0, f0+1, f0+2} (duplicate clamped indices are
// fine: reading the same address twice sums the weights correctly).
__device__ __forceinline__ void axis_taps3(float lo, float binsz, int u,
                                           int idx[3], float w[3]) {
    float g0  = ((float)(2 * u) + 0.5f) * 0.5f;
    float s0  = lo + g0 * binsz;
    float s1  = s0 + 0.5f * binsz;
    float vm0 = (s0 >= -1.0f && s0 <= 16.0f) ? 0.5f : 0.0f;
    float vm1 = (s1 >= -1.0f && s1 <= 16.0f) ? 0.5f : 0.0f;
    float x0  = fminf(fmaxf(s0, 0.0f), 15.0f);
    float x1  = fminf(fmaxf(s1, 0.0f), 15.0f);
    float f0  = floorf(x0);
    float f1  = floorf(x1);
    float l0  = x0 - f0;
    float l1  = x1 - f1;
    bool  same = (f1 == f0);          // else f1 == f0 + 1
    w[0] = (1.0f - l0) * vm0 + (same ? (1.0f - l1) * vm1 : 0.0f);
    w[1] = l0 * vm0 + (same ? l1 * vm1 : (1.0f - l1) * vm1);
    w[2] = same ? 0.0f : l1 * vm1;
    int b  = (int)f0;
    idx[0] = b;
    idx[1] = min(b + 1, 15);
    idx[2] = min(b + 2, 15);
}

// ---------------------------------------------------------------------------
// Kernel 2: aligned RoIAlign (avg, ratio=2), separable 3-tap two-pass.
// Block = (16-channel chunk, roi); 256 threads.
//   x-pass: thread (y, j) gathers 3 taps straight from featp (L1-resident),
//           writes tmp[c][y][j].  (1 sync)
//   y-pass: thread (i, j) combines 3 rows of tmp -> out.
// ---------------------------------------------------------------------------
__global__ __launch_bounds__(256) void roialign_kernel(
        const float* __restrict__ featp,
        const float* __restrict__ rois,
        float* __restrict__ out) {
    const int r     = blockIdx.y;
    const int cbase = blockIdx.x * C_PER;
    const int tid   = threadIdx.x;
    const int lx    = tid & 15;     // output / tmp column j
    const int ly    = tid >> 4;     // x-pass: feature row y | y-pass: out row i

    __shared__ float tmp[C_PER * HH * TSTR];   // 17 KB

    // --- geometry ---
    const float r0  = rois[r * 5 + 0];
    const float bx1 = rois[r * 5 + 1] * SCALE - 0.5f;
    const float by1 = rois[r * 5 + 2] * SCALE - 0.5f;
    const float bx2 = rois[r * 5 + 3] * SCALE - 0.5f;
    const float by2 = rois[r * 5 + 4] * SCALE - 0.5f;
    const int   nb  = (int)r0;
    const float bin_h = (by2 - by1) * (1.0f / OUT_SZ);
    const float bin_w = (bx2 - bx1) * (1.0f / OUT_SZ);

    int XI[3]; float WX[3];
    int YI[3]; float WY[3];
    axis_taps3(bx1, bin_w, lx, XI, WX);
    axis_taps3(by1, bin_h, ly, YI, WY);
    const int YO0 = YI[0] * TSTR, YO1 = YI[1] * TSTR, YO2 = YI[2] * TSTR;

    // --- x-pass: gather 3 taps from featp (global, L1 hits), fill tmp ---
    {
        const float* gp = featp + ((long)nb * C_TOTAL + cbase) * (HH * WW)
                        + ly * WW;
        float* dst = tmp + ly * TSTR + lx;
        #pragma unroll
        for (int c = 0; c < C_PER; c++) {
            const float* row = gp + c * (HH * WW);
            float v;
            v = WX[0] * __ldg(row + XI[0]);
            v = fmaf(WX[1], __ldg(row + XI[1]), v);
            v = fmaf(WX[2], __ldg(row + XI[2]), v);
            dst[c * (HH * TSTR)] = v;
        }
    }
    __syncthreads();

    // --- y-pass: 3 taps from tmp -> out ---
    {
        const float* tc = tmp + lx;
        float* op = out + ((long)r * C_TOTAL + cbase) * (HH * WW) + tid;
        #pragma unroll
        for (int c = 0; c < C_PER; c++) {
            const float* col = tc + c * (HH * TSTR);
            float acc;
            acc = WY[0] * col[YO0];
            acc = fmaf(WY[1], col[YO1], acc);
            acc = fmaf(WY[2], col[YO2], acc);
            op[c * (HH * WW)] = acc;
        }
    }
}

// ---------------------------------------------------------------------------
extern "C" void kernel_launch(void* const* d_in, const int* in_sizes, int n_in,
                              void* d_out, int out_size) {
    const float* feat = (const float*)d_in[0];
    const float* rois = (const float*)d_in[1];
    float* out   = (float*)d_out;
    float* featp = out + OUT_ELEMS;   // feat_p is the 2nd tuple element

    {   // temporal mean
        const int TOTAL4 = FEATP_ELEMS / 4;
        tmean_kernel<<<(TOTAL4 + 255) / 256, 256>>>(feat, featp);
    }
    {   // RoIAlign
        dim3 grid(C_CHUNKS, R_ROIS);   // 128 x 32 = 4096 blocks
        roialign_kernel<<<grid, 256>>>(featp, rois, out);
    }
}

// round 5
// speedup vs baseline: 2.2913x; 1.1107x over previous
#include <cuda_runtime.h>

#define N_BATCH 4
#define C_TOTAL 2048
#define T_FR    8
#define HH      16
#define WW      16
#define R_ROIS  32
#define OUT_SZ  16
#define SCALE   (1.0f/16.0f)

#define C_PER    16
#define C_CHUNKS (C_TOTAL / C_PER)      // 128

#define OUT_ELEMS   (R_ROIS * C_TOTAL * OUT_SZ * OUT_SZ)   // 16777216
#define FEATP_ELEMS (N_BATCH * C_TOTAL * HH * WW)          // 2097152

// ---------------------------------------------------------------------------
// Kernel 1: temporal mean over T=8.  feat [N,C,T,16,16] -> feat_p [N,C,16,16]
// ---------------------------------------------------------------------------
__global__ void tmean_kernel(const float* __restrict__ feat,
                             float* __restrict__ featp) {
    int idx = blockIdx.x * blockDim.x + threadIdx.x;   // float4 index
    const int TOTAL4 = FEATP_ELEMS / 4;                // 524288
    if (idx >= TOTAL4) return;
    const float4* f4 = (const float4*)feat;
    int pix = idx & 63;
    int nc  = idx >> 6;
    long base = (long)nc * (T_FR * 64) + pix;
    float4 a = f4[base];
    #pragma unroll
    for (int t = 1; t < T_FR; t++) {
        float4 v = f4[base + (long)t * 64];
        a.x += v.x; a.y += v.y; a.z += v.z; a.w += v.w;
    }
    a.x *= 0.125f; a.y *= 0.125f; a.z *= 0.125f; a.w *= 0.125f;
    ((float4*)featp)[idx] = a;
}

// 3-tap (index, weight) table for one axis / output coordinate u.
// ratio=2: the two samples' floors differ by <=1, so the 4 bilinear taps fit
// in 3 consecutive cells {f0, f0+1, f0+2}; clamped duplicates just sum.
__device__ __forceinline__ void axis_taps3(float lo, float binsz, int u,
                                           int idx[3], float w[3]) {
    float g0  = ((float)(2 * u) + 0.5f) * 0.5f;
    float s0  = lo + g0 * binsz;
    float s1  = s0 + 0.5f * binsz;
    float vm0 = (s0 >= -1.0f && s0 <= 16.0f) ? 0.5f : 0.0f;
    float vm1 = (s1 >= -1.0f && s1 <= 16.0f) ? 0.5f : 0.0f;
    float x0  = fminf(fmaxf(s0, 0.0f), 15.0f);
    float x1  = fminf(fmaxf(s1, 0.0f), 15.0f);
    float f0  = floorf(x0);
    float f1  = floorf(x1);
    float l0  = x0 - f0;
    float l1  = x1 - f1;
    bool  same = (f1 == f0);          // else f1 == f0 + 1
    w[0] = (1.0f - l0) * vm0 + (same ? (1.0f - l1) * vm1 : 0.0f);
    w[1] = l0 * vm0 + (same ? l1 * vm1 : (1.0f - l1) * vm1);
    w[2] = same ? 0.0f : l1 * vm1;
    int b  = (int)f0;
    idx[0] = b;
    idx[1] = min(b + 1, 15);
    idx[2] = min(b + 2, 15);
}

// ---------------------------------------------------------------------------
// Kernel 2: RoIAlign, separable 3-tap, smem-free.
// Block = (16-channel chunk, roi); 256 threads = output pixels.
// Warp = 2 output rows x 16 columns (lanes 0-15 -> row i, 16-31 -> row i+1).
//   y-pass: thread (i, x=lane&15) gathers 3 feature rows from global
//           (coalesced, L1-resident) -> t(i, x) in a register.
//   x-pass: out(i, j) needs t(i, XI[k]) which lives in lane (lane&16)|XI[k]
//           of the SAME warp -> 3 __shfl_sync. No shared memory, no barriers.
// ---------------------------------------------------------------------------
__global__ __launch_bounds__(256) void roialign_kernel(
        const float* __restrict__ featp,
        const float* __restrict__ rois,
        float* __restrict__ out) {
    const int r     = blockIdx.y;
    const int cbase = blockIdx.x * C_PER;
    const int tid   = threadIdx.x;
    const int lx    = tid & 15;     // column (x for y-pass, j for output)
    const int ly    = tid >> 4;     // output row i
    const int hi    = tid & 16;     // half-warp selector for shuffles

    // --- geometry ---
    const float r0  = rois[r * 5 + 0];
    const float bx1 = rois[r * 5 + 1] * SCALE - 0.5f;
    const float by1 = rois[r * 5 + 2] * SCALE - 0.5f;
    const float bx2 = rois[r * 5 + 3] * SCALE - 0.5f;
    const float by2 = rois[r * 5 + 4] * SCALE - 0.5f;
    const int   nb  = (int)r0;
    const float bin_h = (by2 - by1) * (1.0f / OUT_SZ);
    const float bin_w = (bx2 - bx1) * (1.0f / OUT_SZ);

    int XI[3]; float WX[3];
    int YI[3]; float WY[3];
    axis_taps3(bx1, bin_w, lx, XI, WX);   // taps for MY output column j=lx
    axis_taps3(by1, bin_h, ly, YI, WY);   // taps for MY output row i=ly
    const int YR0 = YI[0] * WW + lx;
    const int YR1 = YI[1] * WW + lx;
    const int YR2 = YI[2] * WW + lx;
    const int S0  = hi | XI[0];
    const int S1  = hi | XI[1];
    const int S2  = hi | XI[2];

    const float* gp = featp + ((long)nb * C_TOTAL + cbase) * (HH * WW);
    float*       op = out   + ((long)r  * C_TOTAL + cbase) * (HH * WW) + tid;

    #pragma unroll
    for (int c = 0; c < C_PER; c++) {
        const float* pl = gp + c * (HH * WW);
        // y-pass (coalesced global reads, L1 hits after first touch)
        float t;
        t =      WY[0] * __ldg(pl + YR0);
        t = fmaf(WY[1], __ldg(pl + YR1), t);
        t = fmaf(WY[2], __ldg(pl + YR2), t);
        // x-pass via intra-half-warp shuffles (zero L1 traffic)
        float v;
        v =      WX[0] * __shfl_sync(0xffffffffu, t, S0);
        v = fmaf(WX[1], __shfl_sync(0xffffffffu, t, S1), v);
        v = fmaf(WX[2], __shfl_sync(0xffffffffu, t, S2), v);
        op[c * (HH * WW)] = v;
    }
}

// ---------------------------------------------------------------------------
extern "C" void kernel_launch(void* const* d_in, const int* in_sizes, int n_in,
                              void* d_out, int out_size) {
    const float* feat = (const float*)d_in[0];
    const float* rois = (const float*)d_in[1];
    float* out   = (float*)d_out;
    float* featp = out + OUT_ELEMS;   // feat_p is the 2nd tuple element

    {   // temporal mean
        const int TOTAL4 = FEATP_ELEMS / 4;
        tmean_kernel<<<(TOTAL4 + 255) / 256, 256>>>(feat, featp);
    }
    {   // RoIAlign
        dim3 grid(C_CHUNKS, R_ROIS);   // 128 x 32 = 4096 blocks
        roialign_kernel<<<grid, 256>>>(featp, rois, out);
    }
}